// round 1
// baseline (speedup 1.0000x reference)
#include <cuda_runtime.h>

// ---------------------------------------------------------------------------
// Problem constants
// ---------------------------------------------------------------------------
#define BB 4
#define CC 32
#define HH 224
#define WW 224
#define HW (HH * WW)              // 50176
#define NPLANE (BB * CC)          // 128
#define NTOT ((size_t)NPLANE * HW)  // 6,422,528 floats = 25.7 MB

// Scratch (no cudaMalloc allowed): x / combined buffer + 4 direction buffers
__device__ float g_x[NTOT];
__device__ float g_dir[4 * NTOT];

// ---------------------------------------------------------------------------
// K0: conv2d 3x3 same, 2 -> 32, writes g_x
// ---------------------------------------------------------------------------
__global__ void conv_in_kernel(const float* __restrict__ y,
                               const float* __restrict__ w3) {
    __shared__ float ws[576];  // [32][2][3][3]
    for (int i = threadIdx.x; i < 576; i += blockDim.x) ws[i] = w3[i];
    __syncthreads();

    int idx = blockIdx.x * blockDim.x + threadIdx.x;
    if (idx >= BB * HW) return;
    int b = idx / HW, pix = idx - b * HW;
    int py = pix / WW, px = pix - py * WW;

    float in[2][3][3];
#pragma unroll
    for (int ic = 0; ic < 2; ic++)
#pragma unroll
        for (int ky = 0; ky < 3; ky++)
#pragma unroll
            for (int kx = 0; kx < 3; kx++) {
                int yy = py + ky - 1, xx = px + kx - 1;
                bool v = ((unsigned)yy < HH) && ((unsigned)xx < WW);
                in[ic][ky][kx] =
                    v ? __ldg(y + ((size_t)(b * 2 + ic)) * HW + yy * WW + xx)
                      : 0.0f;
            }

    for (int oc = 0; oc < 32; oc++) {
        float a = 0.0f;
#pragma unroll
        for (int ic = 0; ic < 2; ic++)
#pragma unroll
            for (int k = 0; k < 9; k++)
                a += in[ic][k / 3][k % 3] * ws[(oc * 2 + ic) * 9 + k];
        g_x[((size_t)(b * 32 + oc)) * HW + pix] = a;
    }
}

// ---------------------------------------------------------------------------
// Scan step: h[s] = (1-a1-a2-a3)*x + a1*hprev[s-1] + a2*hprev[s] + a3*hprev[s+1]
// hbuf has halo at [0] and [225] (always zero); double buffered, 1 bar/step.
// ---------------------------------------------------------------------------
__device__ __forceinline__ void spn_step(float A1, float A2, float A3, float xv,
                                         float (*hbuf)[226], int& cur, int s,
                                         float* __restrict__ yp, int off) {
    float sa = fabsf(A1) + fabsf(A2) + fabsf(A3);
    float inv = __fdividef(1.0f, fmaxf(sa, 1.0f));
    float a1 = A1 * inv, a2 = A2 * inv, a3 = A3 * inv;
    float hn = (1.0f - a1 - a2 - a3) * xv + a1 * hbuf[cur][s] +
               a2 * hbuf[cur][s + 1] + a3 * hbuf[cur][s + 2];
    hbuf[cur ^ 1][s + 1] = hn;
    yp[off] = hn;
    cur ^= 1;
    __syncthreads();
}

// ---------------------------------------------------------------------------
// One directional scan over a (b,c) plane. Thread s = cross-axis index.
// Vertical: t over H, loads coalesced, prefetch groups of 4 steps.
// Horizontal: t over W, per-thread float4 row walk (natural 4-step groups).
// ---------------------------------------------------------------------------
template <bool HOR, bool REV>
__device__ void scan_dir(const float* __restrict__ g1p,
                         const float* __restrict__ g2p,
                         const float* __restrict__ g3p,
                         const float* __restrict__ xp, float* __restrict__ yp,
                         float (*hbuf)[226], int s) {
    int cur = 0;
    if (!HOR) {
        const int dt = REV ? -WW : WW;
        int off = (REV ? (HH - 1) * WW : 0) + s;
        float n1[4], n2[4], n3[4], nx[4];
#pragma unroll
        for (int j = 0; j < 4; j++) {
            int o = off + j * dt;
            n1[j] = __ldg(g1p + o);
            n2[j] = __ldg(g2p + o);
            n3[j] = __ldg(g3p + o);
            nx[j] = __ldg(xp + o);
        }
        for (int tg = 0; tg < 56; tg++) {
            float c1[4], c2[4], c3[4], cx[4];
#pragma unroll
            for (int j = 0; j < 4; j++) {
                c1[j] = n1[j]; c2[j] = n2[j]; c3[j] = n3[j]; cx[j] = nx[j];
            }
            int nb = (tg < 55) ? off + 4 * dt : off;  // clamp (harmless reload)
#pragma unroll
            for (int j = 0; j < 4; j++) {
                int o = nb + j * dt;
                n1[j] = __ldg(g1p + o);
                n2[j] = __ldg(g2p + o);
                n3[j] = __ldg(g3p + o);
                nx[j] = __ldg(xp + o);
            }
#pragma unroll
            for (int j = 0; j < 4; j++)
                spn_step(c1[j], c2[j], c3[j], cx[j], hbuf, cur, s, yp,
                         off + j * dt);
            off += 4 * dt;
        }
    } else {
        const float4* g1v = (const float4*)(g1p + s * WW);
        const float4* g2v = (const float4*)(g2p + s * WW);
        const float4* g3v = (const float4*)(g3p + s * WW);
        const float4* xv4 = (const float4*)(xp + s * WW);
        const int rowo = s * WW;
        int gi = REV ? 55 : 0;
        float4 n1 = __ldg(g1v + gi), n2 = __ldg(g2v + gi);
        float4 n3 = __ldg(g3v + gi), nx = __ldg(xv4 + gi);
        for (int tg = 0; tg < 56; tg++) {
            float4 c1 = n1, c2 = n2, c3 = n3, cx = nx;
            int gn;
            if (REV) gn = (tg < 55) ? 54 - tg : 0;
            else     gn = (tg < 55) ? tg + 1 : 55;
            n1 = __ldg(g1v + gn);
            n2 = __ldg(g2v + gn);
            n3 = __ldg(g3v + gn);
            nx = __ldg(xv4 + gn);
            if (!REV) {
                int t0 = 4 * tg;
                spn_step(c1.x, c2.x, c3.x, cx.x, hbuf, cur, s, yp, rowo + t0);
                spn_step(c1.y, c2.y, c3.y, cx.y, hbuf, cur, s, yp, rowo + t0 + 1);
                spn_step(c1.z, c2.z, c3.z, cx.z, hbuf, cur, s, yp, rowo + t0 + 2);
                spn_step(c1.w, c2.w, c3.w, cx.w, hbuf, cur, s, yp, rowo + t0 + 3);
            } else {
                int t0 = 223 - 4 * tg;
                spn_step(c1.w, c2.w, c3.w, cx.w, hbuf, cur, s, yp, rowo + t0);
                spn_step(c1.z, c2.z, c3.z, cx.z, hbuf, cur, s, yp, rowo + t0 - 1);
                spn_step(c1.y, c2.y, c3.y, cx.y, hbuf, cur, s, yp, rowo + t0 - 2);
                spn_step(c1.x, c2.x, c3.x, cx.x, hbuf, cur, s, yp, rowo + t0 - 3);
            }
        }
    }
}

// ---------------------------------------------------------------------------
// Scan kernel: grid (128 planes, 4 directions), 224 threads.
// Direction map (matches reference): 0=lr (W fwd), 1=rl (H rev),
// 2=du (H fwd), 3=ud (W rev). Direction d uses gate channel groups 3d..3d+2.
// ---------------------------------------------------------------------------
__global__ void __launch_bounds__(224) scan_kernel(
    const float* __restrict__ gates) {
    __shared__ float hbuf[2][226];
    int s = threadIdx.x;         // 0..223
    int plane = blockIdx.x;      // b*32 + c
    int d = blockIdx.y;          // direction
    int b = plane >> 5, c = plane & 31;

    const float* gp = gates + ((size_t)b * 384 + (size_t)(3 * d) * 32 + c) * HW;
    const float* g1p = gp;
    const float* g2p = gp + (size_t)32 * HW;
    const float* g3p = gp + (size_t)64 * HW;
    const float* xp = g_x + (size_t)plane * HW;
    float* yp = g_dir + (size_t)d * NTOT + (size_t)plane * HW;

    hbuf[0][s + 1] = 0.0f;
    if (s < 2) { hbuf[0][s * 225] = 0.0f; hbuf[1][s * 225] = 0.0f; }
    __syncthreads();

    switch (d) {
        case 0:  scan_dir<true,  false>(g1p, g2p, g3p, xp, yp, hbuf, s); break;
        case 1:  scan_dir<false, true >(g1p, g2p, g3p, xp, yp, hbuf, s); break;
        case 2:  scan_dir<false, false>(g1p, g2p, g3p, xp, yp, hbuf, s); break;
        default: scan_dir<true,  true >(g1p, g2p, g3p, xp, yp, hbuf, s); break;
    }
}

// ---------------------------------------------------------------------------
// Combine: g_x = elementwise max over the 4 direction buffers (float4).
// ---------------------------------------------------------------------------
__global__ void combine_kernel() {
    const size_t n4 = NTOT / 4;
    const float4* p0 = (const float4*)g_dir;
    const float4* p1 = (const float4*)(g_dir + NTOT);
    const float4* p2 = (const float4*)(g_dir + 2 * NTOT);
    const float4* p3 = (const float4*)(g_dir + 3 * NTOT);
    float4* o = (float4*)g_x;
    for (size_t i = blockIdx.x * (size_t)blockDim.x + threadIdx.x; i < n4;
         i += (size_t)gridDim.x * blockDim.x) {
        float4 a = __ldg(p0 + i), b = __ldg(p1 + i);
        float4 c = __ldg(p2 + i), d = __ldg(p3 + i);
        float4 r;
        r.x = fmaxf(fmaxf(a.x, b.x), fmaxf(c.x, d.x));
        r.y = fmaxf(fmaxf(a.y, b.y), fmaxf(c.y, d.y));
        r.z = fmaxf(fmaxf(a.z, b.z), fmaxf(c.z, d.z));
        r.w = fmaxf(fmaxf(a.w, b.w), fmaxf(c.w, d.w));
        o[i] = r;
    }
}

// ---------------------------------------------------------------------------
// K3: conv2d 3x3 same 32 -> 2 on g_x, fused log_softmax over the 2 channels.
// ---------------------------------------------------------------------------
__global__ void conv_out_kernel(const float* __restrict__ w4,
                                float* __restrict__ out) {
    __shared__ float ws[576];  // [2][32][3][3]
    for (int i = threadIdx.x; i < 576; i += blockDim.x) ws[i] = w4[i];
    __syncthreads();

    int idx = blockIdx.x * blockDim.x + threadIdx.x;
    if (idx >= BB * HW) return;
    int b = idx / HW, pix = idx - b * HW;
    int py = pix / WW, px = pix - py * WW;

    float a0 = 0.0f, a1 = 0.0f;
    for (int ic = 0; ic < 32; ic++) {
        const float* ip = g_x + ((size_t)(b * 32 + ic)) * HW;
#pragma unroll
        for (int ky = 0; ky < 3; ky++) {
            int yy = py + ky - 1;
            bool vy = (unsigned)yy < HH;
#pragma unroll
            for (int kx = 0; kx < 3; kx++) {
                int xx = px + kx - 1;
                float v = (vy && (unsigned)xx < WW)
                              ? __ldg(ip + yy * WW + xx)
                              : 0.0f;
                int wi = ic * 9 + ky * 3 + kx;
                a0 += v * ws[wi];
                a1 += v * ws[288 + wi];
            }
        }
    }
    float m = fmaxf(a0, a1);
    float l = m + logf(expf(a0 - m) + expf(a1 - m));
    out[(size_t)(b * 2) * HW + pix] = a0 - l;
    out[(size_t)(b * 2 + 1) * HW + pix] = a1 - l;
}

// ---------------------------------------------------------------------------
// Launch: K0 -> scan(pass1) -> combine -> scan(pass2) -> combine -> K3
// All on the default stream (graph-capturable, no allocs, no syncs).
// ---------------------------------------------------------------------------
extern "C" void kernel_launch(void* const* d_in, const int* in_sizes, int n_in,
                              void* d_out, int out_size) {
    const float* gates = (const float*)d_in[0];  // [4,384,224,224]
    const float* y     = (const float*)d_in[1];  // [4,2,224,224]
    const float* w3    = (const float*)d_in[2];  // [32,2,3,3]
    const float* w4    = (const float*)d_in[3];  // [2,32,3,3]
    float* out = (float*)d_out;                  // [4,2,224,224]

    int pxblocks = (BB * HW + 255) / 256;        // 784
    dim3 sg(NPLANE, 4);                          // 512 blocks

    conv_in_kernel<<<pxblocks, 256>>>(y, w3);
    scan_kernel<<<sg, 224>>>(gates);
    combine_kernel<<<2048, 256>>>();
    scan_kernel<<<sg, 224>>>(gates);
    combine_kernel<<<2048, 256>>>();
    conv_out_kernel<<<pxblocks, 256>>>(w4, out);
}

// round 2
// speedup vs baseline: 1.5393x; 1.5393x over previous
#include <cuda_runtime.h>

// ---------------------------------------------------------------------------
// Problem constants
// ---------------------------------------------------------------------------
#define BB 4
#define HH 224
#define WW 224
#define HW (HH * WW)                 // 50176
#define NPLANE 128                   // B*C
#define NTOT ((size_t)NPLANE * HW)   // 6,422,528 floats

#define ST 4            // steps per pipeline stage
#define NS 3            // pipeline stages
#define NGRP (HH / ST)  // 56 groups

// Scratch (no cudaMalloc allowed)
__device__ float g_x[NTOT];
__device__ float g_dir[4 * NTOT];

// ---------------------------------------------------------------------------
// cp.async helpers (LDGSTS)
// ---------------------------------------------------------------------------
__device__ __forceinline__ void cpa16(float* dst, const float* src) {
    unsigned sa = (unsigned)__cvta_generic_to_shared(dst);
    asm volatile("cp.async.cg.shared.global [%0], [%1], 16;" ::"r"(sa), "l"(src));
}
__device__ __forceinline__ void cpa_commit() {
    asm volatile("cp.async.commit_group;");
}
__device__ __forceinline__ void cpa_wait2() {
    asm volatile("cp.async.wait_group 2;");  // NS-1
}

// ---------------------------------------------------------------------------
// K0: conv2d 3x3 same, 2 -> 32, writes g_x
// ---------------------------------------------------------------------------
__global__ void conv_in_kernel(const float* __restrict__ y,
                               const float* __restrict__ w3) {
    __shared__ float ws[576];
    for (int i = threadIdx.x; i < 576; i += blockDim.x) ws[i] = w3[i];
    __syncthreads();

    int idx = blockIdx.x * blockDim.x + threadIdx.x;
    if (idx >= BB * HW) return;
    int b = idx / HW, pix = idx - b * HW;
    int py = pix / WW, px = pix - py * WW;

    float in[2][3][3];
#pragma unroll
    for (int ic = 0; ic < 2; ic++)
#pragma unroll
        for (int ky = 0; ky < 3; ky++)
#pragma unroll
            for (int kx = 0; kx < 3; kx++) {
                int yy = py + ky - 1, xx = px + kx - 1;
                bool v = ((unsigned)yy < HH) && ((unsigned)xx < WW);
                in[ic][ky][kx] =
                    v ? __ldg(y + ((size_t)(b * 2 + ic)) * HW + yy * WW + xx)
                      : 0.0f;
            }

    for (int oc = 0; oc < 32; oc++) {
        float a = 0.0f;
#pragma unroll
        for (int ic = 0; ic < 2; ic++)
#pragma unroll
            for (int k = 0; k < 9; k++)
                a += in[ic][k / 3][k % 3] * ws[(oc * 2 + ic) * 9 + k];
        g_x[((size_t)(b * 32 + oc)) * HW + pix] = a;
    }
}

// ---------------------------------------------------------------------------
// Pipelined directional scan.
//   sbuf[NS][4][ST*224]: staged {g1,g2,g3,x}.
//     vertical layout:   [a][j*224 + s]   (coalesced row per step j)
//     horizontal layout: [a][s*4  + c]    (per-row float4, cols base..base+3)
//   hbuf[2][226]: double-buffered h with zero halo at [0] and [225].
// Chain per step: bar -> 2x LDS(hbuf) -> 3 FMA -> STS -> bar.
// ---------------------------------------------------------------------------
template <bool HOR, bool REV>
__device__ void scan_pipe(const float* __restrict__ g1p,
                          const float* __restrict__ g2p,
                          const float* __restrict__ g3p,
                          const float* __restrict__ xp, float* __restrict__ yp,
                          float (*sbuf)[4][ST * 224], float (*hbuf)[226],
                          int s) {
    const float* garr[4] = {g1p, g2p, g3p, xp};

    // fill one stage slot with time-group tg
    auto fill = [&](int st, int tg) {
        if (HOR) {
            int base = REV ? 220 - 4 * tg : 4 * tg;  // 4-aligned column base
#pragma unroll
            for (int a = 0; a < 4; a++)
                cpa16(&sbuf[st][a][s * 4], garr[a] + s * WW + base);
        } else {
            int j = s / 56, q = s - j * 56;  // step-in-group, 16B chunk
            int row = REV ? 223 - (4 * tg + j) : 4 * tg + j;
#pragma unroll
            for (int a = 0; a < 4; a++)
                cpa16(&sbuf[st][a][j * 224 + q * 4], garr[a] + row * WW + q * 4);
        }
    };

#pragma unroll
    for (int p = 0; p < NS; p++) {
        fill(p, p);
        cpa_commit();
    }

    int cur = 0;
    float hown = 0.0f;

    for (int tg = 0; tg < NGRP; tg++) {
        int st = tg % NS;
        cpa_wait2();
        __syncthreads();  // stage visible to all threads

        // Off-chain: normalize gates + premultiply x for all ST steps.
        float a1[ST], a2[ST], a3[ST], cx[ST];
        if (HOR) {
            float4 G1 = *(const float4*)&sbuf[st][0][s * 4];
            float4 G2 = *(const float4*)&sbuf[st][1][s * 4];
            float4 G3 = *(const float4*)&sbuf[st][2][s * 4];
            float4 Xv = *(const float4*)&sbuf[st][3][s * 4];
            float b1[4] = {G1.x, G1.y, G1.z, G1.w};
            float b2[4] = {G2.x, G2.y, G2.z, G2.w};
            float b3[4] = {G3.x, G3.y, G3.z, G3.w};
            float bx[4] = {Xv.x, Xv.y, Xv.z, Xv.w};
#pragma unroll
            for (int j = 0; j < ST; j++) {
                int c = REV ? 3 - j : j;
                float inv = __fdividef(
                    1.0f, fmaxf(fabsf(b1[c]) + fabsf(b2[c]) + fabsf(b3[c]), 1.0f));
                a1[j] = b1[c] * inv;
                a2[j] = b2[c] * inv;
                a3[j] = b3[c] * inv;
                cx[j] = (1.0f - a1[j] - a2[j] - a3[j]) * bx[c];
            }
        } else {
#pragma unroll
            for (int j = 0; j < ST; j++) {
                float G1 = sbuf[st][0][j * 224 + s];
                float G2 = sbuf[st][1][j * 224 + s];
                float G3 = sbuf[st][2][j * 224 + s];
                float X = sbuf[st][3][j * 224 + s];
                float inv = __fdividef(
                    1.0f, fmaxf(fabsf(G1) + fabsf(G2) + fabsf(G3), 1.0f));
                a1[j] = G1 * inv;
                a2[j] = G2 * inv;
                a3[j] = G3 * inv;
                cx[j] = (1.0f - a1[j] - a2[j] - a3[j]) * X;
            }
        }

        // Serial recurrence steps.
        float hv[ST];
#pragma unroll
        for (int j = 0; j < ST; j++) {
            float hl = hbuf[cur][s];      // h_prev[s-1]
            float hr = hbuf[cur][s + 2];  // h_prev[s+1]
            float hn = fmaf(a1[j], hl,
                            fmaf(a2[j], hown, fmaf(a3[j], hr, cx[j])));
            hbuf[cur ^ 1][s + 1] = hn;
            hown = hn;
            hv[j] = hn;
            cur ^= 1;
            __syncthreads();
            if (!HOR) {
                int row = REV ? 223 - (4 * tg + j) : 4 * tg + j;
                yp[row * WW + s] = hn;  // coalesced
            }
        }
        if (HOR) {
            int base = REV ? 220 - 4 * tg : 4 * tg;
            float4 o;
            if (REV) { o.x = hv[3]; o.y = hv[2]; o.z = hv[1]; o.w = hv[0]; }
            else     { o.x = hv[0]; o.y = hv[1]; o.z = hv[2]; o.w = hv[3]; }
            *(float4*)(yp + s * WW + base) = o;
        }

        int nt = tg + NS;
        if (nt < NGRP) fill(st, nt);
        cpa_commit();  // empty group in the tail keeps wait counts aligned
    }
}

// ---------------------------------------------------------------------------
// Scan kernel: grid (128 planes, 4 directions), 224 threads.
// d: 0=lr (W fwd), 1=rl (H rev), 2=du (H fwd), 3=ud (W rev);
// direction d uses gate channel groups 3d..3d+2 (matches reference).
// ---------------------------------------------------------------------------
__global__ void __launch_bounds__(224) scan_kernel(
    const float* __restrict__ gates) {
    __shared__ float sbuf[NS][4][ST * 224];  // 43008 B
    __shared__ float hbuf[2][226];           //  1808 B

    int s = threadIdx.x;
    int plane = blockIdx.x;
    int d = blockIdx.y;
    int b = plane >> 5, c = plane & 31;

    const float* gp = gates + ((size_t)b * 384 + (size_t)(3 * d) * 32 + c) * HW;
    const float* g1p = gp;
    const float* g2p = gp + (size_t)32 * HW;
    const float* g3p = gp + (size_t)64 * HW;
    const float* xp = g_x + (size_t)plane * HW;
    float* yp = g_dir + (size_t)d * NTOT + (size_t)plane * HW;

    hbuf[0][s + 1] = 0.0f;
    if (s < 2) { hbuf[0][s * 225] = 0.0f; hbuf[1][s * 225] = 0.0f; }
    __syncthreads();

    switch (d) {
        case 0:  scan_pipe<true,  false>(g1p, g2p, g3p, xp, yp, sbuf, hbuf, s); break;
        case 1:  scan_pipe<false, true >(g1p, g2p, g3p, xp, yp, sbuf, hbuf, s); break;
        case 2:  scan_pipe<false, false>(g1p, g2p, g3p, xp, yp, sbuf, hbuf, s); break;
        default: scan_pipe<true,  true >(g1p, g2p, g3p, xp, yp, sbuf, hbuf, s); break;
    }
}

// ---------------------------------------------------------------------------
// Combine: g_x = elementwise max over the 4 direction buffers (float4).
// ---------------------------------------------------------------------------
__global__ void combine_kernel() {
    const size_t n4 = NTOT / 4;
    const float4* p0 = (const float4*)g_dir;
    const float4* p1 = (const float4*)(g_dir + NTOT);
    const float4* p2 = (const float4*)(g_dir + 2 * NTOT);
    const float4* p3 = (const float4*)(g_dir + 3 * NTOT);
    float4* o = (float4*)g_x;
    for (size_t i = blockIdx.x * (size_t)blockDim.x + threadIdx.x; i < n4;
         i += (size_t)gridDim.x * blockDim.x) {
        float4 a = __ldg(p0 + i), b = __ldg(p1 + i);
        float4 c = __ldg(p2 + i), d = __ldg(p3 + i);
        float4 r;
        r.x = fmaxf(fmaxf(a.x, b.x), fmaxf(c.x, d.x));
        r.y = fmaxf(fmaxf(a.y, b.y), fmaxf(c.y, d.y));
        r.z = fmaxf(fmaxf(a.z, b.z), fmaxf(c.z, d.z));
        r.w = fmaxf(fmaxf(a.w, b.w), fmaxf(c.w, d.w));
        o[i] = r;
    }
}

// ---------------------------------------------------------------------------
// K3: conv2d 3x3 same 32 -> 2 on g_x, fused log_softmax over the 2 channels.
// ---------------------------------------------------------------------------
__global__ void conv_out_kernel(const float* __restrict__ w4,
                                float* __restrict__ out) {
    __shared__ float ws[576];
    for (int i = threadIdx.x; i < 576; i += blockDim.x) ws[i] = w4[i];
    __syncthreads();

    int idx = blockIdx.x * blockDim.x + threadIdx.x;
    if (idx >= BB * HW) return;
    int b = idx / HW, pix = idx - b * HW;
    int py = pix / WW, px = pix - py * WW;

    float a0 = 0.0f, a1 = 0.0f;
    for (int ic = 0; ic < 32; ic++) {
        const float* ip = g_x + ((size_t)(b * 32 + ic)) * HW;
#pragma unroll
        for (int ky = 0; ky < 3; ky++) {
            int yy = py + ky - 1;
            bool vy = (unsigned)yy < HH;
#pragma unroll
            for (int kx = 0; kx < 3; kx++) {
                int xx = px + kx - 1;
                float v = (vy && (unsigned)xx < WW)
                              ? __ldg(ip + yy * WW + xx)
                              : 0.0f;
                int wi = ic * 9 + ky * 3 + kx;
                a0 += v * ws[wi];
                a1 += v * ws[288 + wi];
            }
        }
    }
    float m = fmaxf(a0, a1);
    float l = m + logf(expf(a0 - m) + expf(a1 - m));
    out[(size_t)(b * 2) * HW + pix] = a0 - l;
    out[(size_t)(b * 2 + 1) * HW + pix] = a1 - l;
}

// ---------------------------------------------------------------------------
// Launch: K0 -> scan(pass1) -> combine -> scan(pass2) -> combine -> K3
// ---------------------------------------------------------------------------
extern "C" void kernel_launch(void* const* d_in, const int* in_sizes, int n_in,
                              void* d_out, int out_size) {
    const float* gates = (const float*)d_in[0];
    const float* y     = (const float*)d_in[1];
    const float* w3    = (const float*)d_in[2];
    const float* w4    = (const float*)d_in[3];
    float* out = (float*)d_out;

    int pxblocks = (BB * HW + 255) / 256;
    dim3 sg(NPLANE, 4);

    conv_in_kernel<<<pxblocks, 256>>>(y, w3);
    scan_kernel<<<sg, 224>>>(gates);
    combine_kernel<<<2048, 256>>>();
    scan_kernel<<<sg, 224>>>(gates);
    combine_kernel<<<2048, 256>>>();
    conv_out_kernel<<<pxblocks, 256>>>(w4, out);
}